// round 1
// baseline (speedup 1.0000x reference)
#include <cuda_runtime.h>

// ---------------------------------------------------------------------------
// RegionAttention: x(16384,512) -> qkv gemm -> per-(region,head) attention with
// EPEG conv (depthwise k=5 along query axis) + softmax -> proj gemm -> out.
// 16 regions x 1024 tokens, 8 heads x 64 dim. All fp32.
// ---------------------------------------------------------------------------

#define LTOK   16384
#define DIMC   512
#define QKVC   1536
#define NH     8
#define HD     64
#define NREG   1024
#define SCALE_Q 0.125f   // 64^-0.5

// scratch (static device allocations are allowed)
__device__ float g_qkv[LTOK * QKVC];   // (l, 3*512): q at +0, k at +512, v at +1024
__device__ float g_att[LTOK * DIMC];   // attention output in token order

// region token (rg, n) -> original token index l
__device__ __forceinline__ int tok_index(int rg, int n) {
    // bi = rg>>2, bj = rg&3, ri = n>>5, rj = n&31
    return ((rg >> 2) << 12) | ((n >> 5) << 7) | ((rg & 3) << 5) | (n & 31);
}

// ---------------------------------------------------------------------------
// Generic C[m,n] = sum_k A[m,k] * W[n,k] + bias[n]
// BM=BN=128, BK=16, 256 threads, 8x8 per thread. M,N,K divisible by tiles.
// ---------------------------------------------------------------------------
__global__ __launch_bounds__(256) void gemm_bias_kernel(
    const float* __restrict__ A, const float* __restrict__ W,
    const float* __restrict__ bias, float* __restrict__ C,
    int M, int N, int K)
{
    __shared__ float AsT[16][132];
    __shared__ float WsT[16][132];

    const int tid = threadIdx.x;
    const int m0 = blockIdx.y << 7;
    const int n0 = blockIdx.x << 7;
    const int ty = tid >> 4;          // 0..15
    const int tx = tid & 15;          // 0..15
    const int lr = tid >> 2;          // 0..63
    const int lc = (tid & 3) << 2;    // 0,4,8,12

    float acc[8][8];
#pragma unroll
    for (int i = 0; i < 8; i++)
#pragma unroll
        for (int j = 0; j < 8; j++) acc[i][j] = 0.f;

    const float* Ap = A + (size_t)(m0 + lr) * K + lc;
    const float* Wp = W + (size_t)(n0 + lr) * K + lc;

    for (int k0 = 0; k0 < K; k0 += 16) {
        float4 a0 = *(const float4*)(Ap + k0);
        float4 a1 = *(const float4*)(Ap + (size_t)64 * K + k0);
        float4 w0 = *(const float4*)(Wp + k0);
        float4 w1 = *(const float4*)(Wp + (size_t)64 * K + k0);
        __syncthreads();
        AsT[lc + 0][lr] = a0.x; AsT[lc + 1][lr] = a0.y;
        AsT[lc + 2][lr] = a0.z; AsT[lc + 3][lr] = a0.w;
        AsT[lc + 0][lr + 64] = a1.x; AsT[lc + 1][lr + 64] = a1.y;
        AsT[lc + 2][lr + 64] = a1.z; AsT[lc + 3][lr + 64] = a1.w;
        WsT[lc + 0][lr] = w0.x; WsT[lc + 1][lr] = w0.y;
        WsT[lc + 2][lr] = w0.z; WsT[lc + 3][lr] = w0.w;
        WsT[lc + 0][lr + 64] = w1.x; WsT[lc + 1][lr + 64] = w1.y;
        WsT[lc + 2][lr + 64] = w1.z; WsT[lc + 3][lr + 64] = w1.w;
        __syncthreads();
#pragma unroll 8
        for (int kk = 0; kk < 16; kk++) {
            float af[8], wf[8];
            *(float4*)(af)     = *(const float4*)(&AsT[kk][ty * 8]);
            *(float4*)(af + 4) = *(const float4*)(&AsT[kk][ty * 8 + 4]);
            *(float4*)(wf)     = *(const float4*)(&WsT[kk][tx * 8]);
            *(float4*)(wf + 4) = *(const float4*)(&WsT[kk][tx * 8 + 4]);
#pragma unroll
            for (int i = 0; i < 8; i++)
#pragma unroll
                for (int j = 0; j < 8; j++)
                    acc[i][j] += af[i] * wf[j];
        }
    }

    float bv[8];
#pragma unroll
    for (int j = 0; j < 8; j++) bv[j] = bias[n0 + tx * 8 + j];

#pragma unroll
    for (int i = 0; i < 8; i++) {
        float* Cp = C + (size_t)(m0 + ty * 8 + i) * N + n0 + tx * 8;
        float4 o0 = make_float4(acc[i][0] + bv[0], acc[i][1] + bv[1],
                                acc[i][2] + bv[2], acc[i][3] + bv[3]);
        float4 o1 = make_float4(acc[i][4] + bv[4], acc[i][5] + bv[5],
                                acc[i][6] + bv[6], acc[i][7] + bv[7]);
        *(float4*)(Cp)     = o0;
        *(float4*)(Cp + 4) = o1;
    }
}

// ---------------------------------------------------------------------------
// Fused region attention.
// grid: (row_tile 0..7, head 0..7, region 0..15), 256 threads.
// Per CTA: 128 output rows; S extended by +-2 halo rows (132) for the conv.
// Streams over 16 j-tiles of 64 keys with online softmax.
// ---------------------------------------------------------------------------
#define SMEM_ATTN_BYTES (35472 * 4)

__global__ __launch_bounds__(256) void region_attn_kernel(
    const float* __restrict__ epeg_w, const float* __restrict__ epeg_b)
{
    extern __shared__ float sm[];
    float* QsT     = sm;                 // [64][136] (cols 0..127 main rows, 128..131 halo)
    float* KsT     = sm + 8704;          // [64][68]
    float* Vs      = sm + 13056;         // [64][68]  row-major (j, d)
    float* Ss      = sm + 17408;         // [132][68] row p <-> region row i0-2+p
    float* PsT     = sm + 26384;         // [64][136] (j, row)
    float* alpha_s = sm + 35088;         // [128]
    float* m_row   = sm + 35216;         // [128]
    float* l_row   = sm + 35344;         // [128]

    const int tid  = threadIdx.x;
    const int it   = blockIdx.x;
    const int h    = blockIdx.y;
    const int rg   = blockIdx.z;
    const int i0   = it << 7;

    const int ty   = tid >> 4;   // 0..15
    const int tx   = tid & 15;   // 0..15
    const int warp = tid >> 5;   // 0..7
    const int lane = tid & 31;

    const float cw0 = epeg_w[h * 5 + 0];
    const float cw1 = epeg_w[h * 5 + 1];
    const float cw2 = epeg_w[h * 5 + 2];
    const float cw3 = epeg_w[h * 5 + 3];
    const float cw4 = epeg_w[h * 5 + 4];
    const float cb  = epeg_b[h];

    if (tid < 128) { m_row[tid] = -3.0e38f; l_row[tid] = 0.f; }

    // ---- load Q (scaled), transposed to (d, row-col), zero out-of-region halo
    for (int idx = tid; idx < 132 * 16; idx += 256) {
        int p  = idx >> 4;            // 0..131 (Ss row index)
        int c4 = (idx & 15) << 2;     // d base
        int col = (p < 2) ? (128 + p) : ((p < 130) ? (p - 2) : p);
        int ireg = i0 - 2 + p;
        float4 q = make_float4(0.f, 0.f, 0.f, 0.f);
        if (ireg >= 0 && ireg < NREG) {
            int l = tok_index(rg, ireg);
            q = *(const float4*)(g_qkv + (size_t)l * QKVC + h * HD + c4);
        }
        QsT[(c4 + 0) * 136 + col] = q.x * SCALE_Q;
        QsT[(c4 + 1) * 136 + col] = q.y * SCALE_Q;
        QsT[(c4 + 2) * 136 + col] = q.z * SCALE_Q;
        QsT[(c4 + 3) * 136 + col] = q.w * SCALE_Q;
    }

    float accO[8][4];
#pragma unroll
    for (int i = 0; i < 8; i++)
#pragma unroll
        for (int j = 0; j < 4; j++) accO[i][j] = 0.f;

    __syncthreads();

    for (int jt = 0; jt < 16; jt++) {
        // ---- load K (transposed) and V tiles
        for (int idx = tid; idx < 64 * 16; idx += 256) {
            int j  = idx >> 4;
            int c4 = (idx & 15) << 2;
            int l  = tok_index(rg, (jt << 6) + j);
            const float* base = g_qkv + (size_t)l * QKVC + h * HD + c4;
            float4 k4 = *(const float4*)(base + 512);
            float4 v4 = *(const float4*)(base + 1024);
            KsT[(c4 + 0) * 68 + j] = k4.x;
            KsT[(c4 + 1) * 68 + j] = k4.y;
            KsT[(c4 + 2) * 68 + j] = k4.z;
            KsT[(c4 + 3) * 68 + j] = k4.w;
            *(float4*)(Vs + j * 68 + c4) = v4;
        }
        __syncthreads();

        // ---- S = Qscaled @ K^T : main 128x64 (8x4 per thread)
        {
            float accS[8][4];
#pragma unroll
            for (int i = 0; i < 8; i++)
#pragma unroll
                for (int j = 0; j < 4; j++) accS[i][j] = 0.f;

#pragma unroll 8
            for (int d = 0; d < 64; d++) {
                float af[8], bf[4];
                *(float4*)(af)     = *(const float4*)(QsT + d * 136 + ty * 8);
                *(float4*)(af + 4) = *(const float4*)(QsT + d * 136 + ty * 8 + 4);
                *(float4*)(bf)     = *(const float4*)(KsT + d * 68 + tx * 4);
#pragma unroll
                for (int i = 0; i < 8; i++)
#pragma unroll
                    for (int j = 0; j < 4; j++)
                        accS[i][j] += af[i] * bf[j];
            }
#pragma unroll
            for (int i = 0; i < 8; i++) {
                float4 s4 = make_float4(accS[i][0], accS[i][1], accS[i][2], accS[i][3]);
                *(float4*)(Ss + (ty * 8 + i + 2) * 68 + tx * 4) = s4;
            }

            // ---- halo rows: 4 rows x 64 cols, one dot per thread
            int hr = tid >> 6;      // 0..3
            int j  = tid & 63;
            float a = 0.f;
#pragma unroll 8
            for (int d = 0; d < 64; d++)
                a += QsT[d * 136 + 128 + hr] * KsT[d * 68 + j];
            int ps = (hr < 2) ? hr : (128 + hr);   // 0,1,130,131
            Ss[ps * 68 + j] = a;
        }
        __syncthreads();

        // ---- conv + bias + online softmax (warp w owns rows w*16..w*16+15)
        for (int rr = 0; rr < 16; rr++) {
            int r = (warp << 4) + rr;
            float lg0, lg1;
            {
                int j = lane;
                float s0 = Ss[(r + 0) * 68 + j];
                float s1 = Ss[(r + 1) * 68 + j];
                float s2 = Ss[(r + 2) * 68 + j];
                float s3 = Ss[(r + 3) * 68 + j];
                float s4 = Ss[(r + 4) * 68 + j];
                lg0 = s2 + cb + cw0 * s0 + cw1 * s1 + cw2 * s2 + cw3 * s3 + cw4 * s4;
            }
            {
                int j = lane + 32;
                float s0 = Ss[(r + 0) * 68 + j];
                float s1 = Ss[(r + 1) * 68 + j];
                float s2 = Ss[(r + 2) * 68 + j];
                float s3 = Ss[(r + 3) * 68 + j];
                float s4 = Ss[(r + 4) * 68 + j];
                lg1 = s2 + cb + cw0 * s0 + cw1 * s1 + cw2 * s2 + cw3 * s3 + cw4 * s4;
            }
            float mx = fmaxf(lg0, lg1);
#pragma unroll
            for (int off = 16; off > 0; off >>= 1)
                mx = fmaxf(mx, __shfl_xor_sync(0xffffffffu, mx, off));
            float m_old = m_row[r];
            float m_new = fmaxf(m_old, mx);
            float p0 = __expf(lg0 - m_new);
            float p1 = __expf(lg1 - m_new);
            float rs = p0 + p1;
#pragma unroll
            for (int off = 16; off > 0; off >>= 1)
                rs += __shfl_xor_sync(0xffffffffu, rs, off);
            if (lane == 0) {
                float alpha = __expf(m_old - m_new);
                l_row[r] = l_row[r] * alpha + rs;
                m_row[r] = m_new;
                alpha_s[r] = alpha;
            }
            PsT[lane * 136 + r]        = p0;
            PsT[(lane + 32) * 136 + r] = p1;
        }
        __syncthreads();

        // ---- O = O*alpha + P @ V  (8x4 per thread)
        {
#pragma unroll
            for (int i = 0; i < 8; i++) {
                float al = alpha_s[ty * 8 + i];
#pragma unroll
                for (int j = 0; j < 4; j++) accO[i][j] *= al;
            }
#pragma unroll 4
            for (int j = 0; j < 64; j++) {
                float pf[8], vf[4];
                *(float4*)(pf)     = *(const float4*)(PsT + j * 136 + ty * 8);
                *(float4*)(pf + 4) = *(const float4*)(PsT + j * 136 + ty * 8 + 4);
                *(float4*)(vf)     = *(const float4*)(Vs + j * 68 + tx * 4);
#pragma unroll
                for (int i = 0; i < 8; i++)
#pragma unroll
                    for (int c = 0; c < 4; c++)
                        accO[i][c] += pf[i] * vf[c];
            }
        }
        __syncthreads();
    }

    // ---- normalize and write to g_att in token order (undoes region permute)
#pragma unroll
    for (int i = 0; i < 8; i++) {
        int r = ty * 8 + i;
        float inv = 1.0f / l_row[r];
        int l = tok_index(rg, i0 + r);
        float4 o = make_float4(accO[i][0] * inv, accO[i][1] * inv,
                               accO[i][2] * inv, accO[i][3] * inv);
        *(float4*)(g_att + (size_t)l * DIMC + h * HD + tx * 4) = o;
    }
}

// ---------------------------------------------------------------------------
extern "C" void kernel_launch(void* const* d_in, const int* in_sizes, int n_in,
                              void* d_out, int out_size) {
    const float* x      = (const float*)d_in[0];
    const float* qkv_w  = (const float*)d_in[1];
    const float* qkv_b  = (const float*)d_in[2];
    const float* proj_w = (const float*)d_in[3];
    const float* proj_b = (const float*)d_in[4];
    const float* epeg_w = (const float*)d_in[5];
    const float* epeg_b = (const float*)d_in[6];
    float* out = (float*)d_out;

    float* qkv_buf = nullptr;
    float* att_buf = nullptr;
    cudaGetSymbolAddress((void**)&qkv_buf, g_qkv);
    cudaGetSymbolAddress((void**)&att_buf, g_att);

    cudaFuncSetAttribute(region_attn_kernel,
                         cudaFuncAttributeMaxDynamicSharedMemorySize,
                         SMEM_ATTN_BYTES);

    dim3 blk(256);

    // qkv = x @ qkv_w^T + qkv_b
    gemm_bias_kernel<<<dim3(QKVC / 128, LTOK / 128), blk>>>(
        x, qkv_w, qkv_b, qkv_buf, LTOK, QKVC, DIMC);

    // fused region attention (writes g_att in token order)
    region_attn_kernel<<<dim3(8, NH, 16), blk, SMEM_ATTN_BYTES>>>(epeg_w, epeg_b);

    // out = att @ proj_w^T + proj_b
    gemm_bias_kernel<<<dim3(DIMC / 128, LTOK / 128), blk>>>(
        att_buf, proj_w, proj_b, out, LTOK, DIMC, DIMC);
}

// round 3
// speedup vs baseline: 1.1181x; 1.1181x over previous
#include <cuda_runtime.h>

// ---------------------------------------------------------------------------
// RegionAttention: x(16384,512) -> qkv gemm -> per-(region,head) attention with
// EPEG conv (depthwise k=5 along query axis) + softmax -> proj gemm -> out.
// 16 regions x 1024 tokens, 8 heads x 64 dim. All fp32.
// R3 (= R2 resubmit after infra failure): attention tile 64 rows, smem 88KB
// -> 2 CTAs/SM.
// ---------------------------------------------------------------------------

#define LTOK   16384
#define DIMC   512
#define QKVC   1536
#define NH     8
#define HD     64
#define NREG   1024
#define SCALE_Q 0.125f   // 64^-0.5

__device__ float g_qkv[LTOK * QKVC];   // (l, 3*512): q at +0, k at +512, v at +1024
__device__ float g_att[LTOK * DIMC];   // attention output in token order

// region token (rg, n) -> original token index l
__device__ __forceinline__ int tok_index(int rg, int n) {
    return ((rg >> 2) << 12) | ((n >> 5) << 7) | ((rg & 3) << 5) | (n & 31);
}

// ---------------------------------------------------------------------------
// Generic C[m,n] = sum_k A[m,k] * W[n,k] + bias[n]
// BM=BN=128, BK=16, 256 threads, 8x8 per thread.
// ---------------------------------------------------------------------------
__global__ __launch_bounds__(256) void gemm_bias_kernel(
    const float* __restrict__ A, const float* __restrict__ W,
    const float* __restrict__ bias, float* __restrict__ C,
    int M, int N, int K)
{
    __shared__ float AsT[16][132];
    __shared__ float WsT[16][132];

    const int tid = threadIdx.x;
    const int m0 = blockIdx.y << 7;
    const int n0 = blockIdx.x << 7;
    const int ty = tid >> 4;
    const int tx = tid & 15;
    const int lr = tid >> 2;
    const int lc = (tid & 3) << 2;

    float acc[8][8];
#pragma unroll
    for (int i = 0; i < 8; i++)
#pragma unroll
        for (int j = 0; j < 8; j++) acc[i][j] = 0.f;

    const float* Ap = A + (size_t)(m0 + lr) * K + lc;
    const float* Wp = W + (size_t)(n0 + lr) * K + lc;

    for (int k0 = 0; k0 < K; k0 += 16) {
        float4 a0 = *(const float4*)(Ap + k0);
        float4 a1 = *(const float4*)(Ap + (size_t)64 * K + k0);
        float4 w0 = *(const float4*)(Wp + k0);
        float4 w1 = *(const float4*)(Wp + (size_t)64 * K + k0);
        __syncthreads();
        AsT[lc + 0][lr] = a0.x; AsT[lc + 1][lr] = a0.y;
        AsT[lc + 2][lr] = a0.z; AsT[lc + 3][lr] = a0.w;
        AsT[lc + 0][lr + 64] = a1.x; AsT[lc + 1][lr + 64] = a1.y;
        AsT[lc + 2][lr + 64] = a1.z; AsT[lc + 3][lr + 64] = a1.w;
        WsT[lc + 0][lr] = w0.x; WsT[lc + 1][lr] = w0.y;
        WsT[lc + 2][lr] = w0.z; WsT[lc + 3][lr] = w0.w;
        WsT[lc + 0][lr + 64] = w1.x; WsT[lc + 1][lr + 64] = w1.y;
        WsT[lc + 2][lr + 64] = w1.z; WsT[lc + 3][lr + 64] = w1.w;
        __syncthreads();
#pragma unroll 8
        for (int kk = 0; kk < 16; kk++) {
            float af[8], wf[8];
            *(float4*)(af)     = *(const float4*)(&AsT[kk][ty * 8]);
            *(float4*)(af + 4) = *(const float4*)(&AsT[kk][ty * 8 + 4]);
            *(float4*)(wf)     = *(const float4*)(&WsT[kk][tx * 8]);
            *(float4*)(wf + 4) = *(const float4*)(&WsT[kk][tx * 8 + 4]);
#pragma unroll
            for (int i = 0; i < 8; i++)
#pragma unroll
                for (int j = 0; j < 8; j++)
                    acc[i][j] += af[i] * wf[j];
        }
    }

    float bv[8];
#pragma unroll
    for (int j = 0; j < 8; j++) bv[j] = bias[n0 + tx * 8 + j];

#pragma unroll
    for (int i = 0; i < 8; i++) {
        float* Cp = C + (size_t)(m0 + ty * 8 + i) * N + n0 + tx * 8;
        *(float4*)(Cp)     = make_float4(acc[i][0] + bv[0], acc[i][1] + bv[1],
                                         acc[i][2] + bv[2], acc[i][3] + bv[3]);
        *(float4*)(Cp + 4) = make_float4(acc[i][4] + bv[4], acc[i][5] + bv[5],
                                         acc[i][6] + bv[6], acc[i][7] + bv[7]);
    }
}

// ---------------------------------------------------------------------------
// Fused region attention, 64-row Q tiles.
// grid: (row_tile 0..15, head 0..7, region 0..15), 256 threads, 2 CTAs/SM.
// S extended by +-2 halo rows (68) for the conv along query axis.
// Streams over 16 j-tiles of 64 keys with online softmax.
// ---------------------------------------------------------------------------
// smem float offsets
#define OFF_QST   0        // [64 d][72]  cols 0..63 main rows, 64..67 halo
#define OFF_KST   4608     // [64 d][68]
#define OFF_VS    8960     // [64 j][68]
#define OFF_SS    13312    // [68 p][68]  p <-> region row i0-2+p
#define OFF_PST   17936    // [64 j][68]  (j, row)
#define OFF_ALPHA 22288    // [64]
#define OFF_M     22352    // [64]
#define OFF_L     22416    // [64]
#define SMEM_ATTN_FLOATS 22480
#define SMEM_ATTN_BYTES (SMEM_ATTN_FLOATS * 4)

__global__ __launch_bounds__(256) void region_attn_kernel(
    const float* __restrict__ epeg_w, const float* __restrict__ epeg_b)
{
    extern __shared__ float sm[];
    float* QsT     = sm + OFF_QST;
    float* KsT     = sm + OFF_KST;
    float* Vs      = sm + OFF_VS;
    float* Ss      = sm + OFF_SS;
    float* PsT     = sm + OFF_PST;
    float* alpha_s = sm + OFF_ALPHA;
    float* m_row   = sm + OFF_M;
    float* l_row   = sm + OFF_L;

    const int tid  = threadIdx.x;
    const int it   = blockIdx.x;
    const int h    = blockIdx.y;
    const int rg   = blockIdx.z;
    const int i0   = it << 6;

    const int ty   = tid >> 4;   // 0..15
    const int tx   = tid & 15;   // 0..15
    const int warp = tid >> 5;   // 0..7
    const int lane = tid & 31;

    const float cw0 = epeg_w[h * 5 + 0];
    const float cw1 = epeg_w[h * 5 + 1];
    const float cw2 = epeg_w[h * 5 + 2];
    const float cw3 = epeg_w[h * 5 + 3];
    const float cw4 = epeg_w[h * 5 + 4];
    const float cb  = epeg_b[h];

    if (tid < 64) { m_row[tid] = -3.0e38f; l_row[tid] = 0.f; }

    // ---- load Q (scaled), transposed to (d, row-col); zero out-of-region halo
    for (int idx = tid; idx < 68 * 16; idx += 256) {
        int p  = idx >> 4;            // 0..67 (Ss row index)
        int c4 = (idx & 15) << 2;     // d base
        int col = (p < 2) ? (64 + p) : ((p < 66) ? (p - 2) : p);
        int ireg = i0 - 2 + p;
        float4 q = make_float4(0.f, 0.f, 0.f, 0.f);
        if (ireg >= 0 && ireg < NREG) {
            int l = tok_index(rg, ireg);
            q = *(const float4*)(g_qkv + (size_t)l * QKVC + h * HD + c4);
        }
        QsT[(c4 + 0) * 72 + col] = q.x * SCALE_Q;
        QsT[(c4 + 1) * 72 + col] = q.y * SCALE_Q;
        QsT[(c4 + 2) * 72 + col] = q.z * SCALE_Q;
        QsT[(c4 + 3) * 72 + col] = q.w * SCALE_Q;
    }

    float accO[4][4];
#pragma unroll
    for (int i = 0; i < 4; i++)
#pragma unroll
        for (int j = 0; j < 4; j++) accO[i][j] = 0.f;

    __syncthreads();

    for (int jt = 0; jt < 16; jt++) {
        // ---- load K (transposed) and V tiles
        for (int idx = tid; idx < 64 * 16; idx += 256) {
            int j  = idx >> 4;
            int c4 = (idx & 15) << 2;
            int l  = tok_index(rg, (jt << 6) + j);
            const float* base = g_qkv + (size_t)l * QKVC + h * HD + c4;
            float4 k4 = *(const float4*)(base + 512);
            float4 v4 = *(const float4*)(base + 1024);
            KsT[(c4 + 0) * 68 + j] = k4.x;
            KsT[(c4 + 1) * 68 + j] = k4.y;
            KsT[(c4 + 2) * 68 + j] = k4.z;
            KsT[(c4 + 3) * 68 + j] = k4.w;
            *(float4*)(Vs + j * 68 + c4) = v4;
        }
        __syncthreads();

        // ---- S = Qscaled @ K^T : main 64x64 (4x4 per thread)
        {
            float accS[4][4];
#pragma unroll
            for (int i = 0; i < 4; i++)
#pragma unroll
                for (int j = 0; j < 4; j++) accS[i][j] = 0.f;

#pragma unroll 8
            for (int d = 0; d < 64; d++) {
                float af[4], bf[4];
                *(float4*)(af) = *(const float4*)(QsT + d * 72 + ty * 4);
                *(float4*)(bf) = *(const float4*)(KsT + d * 68 + tx * 4);
#pragma unroll
                for (int i = 0; i < 4; i++)
#pragma unroll
                    for (int j = 0; j < 4; j++)
                        accS[i][j] += af[i] * bf[j];
            }
#pragma unroll
            for (int i = 0; i < 4; i++) {
                *(float4*)(Ss + (ty * 4 + i + 2) * 68 + tx * 4) =
                    make_float4(accS[i][0], accS[i][1], accS[i][2], accS[i][3]);
            }

            // ---- halo rows: 4 rows x 64 cols, one dot per thread
            int hr = tid >> 6;      // 0..3
            int j  = tid & 63;
            float a = 0.f;
#pragma unroll 8
            for (int d = 0; d < 64; d++)
                a += QsT[d * 72 + 64 + hr] * KsT[d * 68 + j];
            int ps = (hr < 2) ? hr : (64 + hr);   // 0,1,66,67
            Ss[ps * 68 + j] = a;
        }
        __syncthreads();

        // ---- conv + bias + online softmax (warp w owns rows w*8..w*8+7)
        for (int rr = 0; rr < 8; rr++) {
            int r = (warp << 3) + rr;
            float lg0, lg1;
            {
                int j = lane;
                float s0 = Ss[(r + 0) * 68 + j];
                float s1 = Ss[(r + 1) * 68 + j];
                float s2 = Ss[(r + 2) * 68 + j];
                float s3 = Ss[(r + 3) * 68 + j];
                float s4 = Ss[(r + 4) * 68 + j];
                lg0 = s2 + cb + cw0 * s0 + cw1 * s1 + cw2 * s2 + cw3 * s3 + cw4 * s4;
            }
            {
                int j = lane + 32;
                float s0 = Ss[(r + 0) * 68 + j];
                float s1 = Ss[(r + 1) * 68 + j];
                float s2 = Ss[(r + 2) * 68 + j];
                float s3 = Ss[(r + 3) * 68 + j];
                float s4 = Ss[(r + 4) * 68 + j];
                lg1 = s2 + cb + cw0 * s0 + cw1 * s1 + cw2 * s2 + cw3 * s3 + cw4 * s4;
            }
            float mx = fmaxf(lg0, lg1);
#pragma unroll
            for (int off = 16; off > 0; off >>= 1)
                mx = fmaxf(mx, __shfl_xor_sync(0xffffffffu, mx, off));
            float m_old = m_row[r];
            float m_new = fmaxf(m_old, mx);
            float p0 = __expf(lg0 - m_new);
            float p1 = __expf(lg1 - m_new);
            float rs = p0 + p1;
#pragma unroll
            for (int off = 16; off > 0; off >>= 1)
                rs += __shfl_xor_sync(0xffffffffu, rs, off);
            if (lane == 0) {
                float alpha = __expf(m_old - m_new);
                l_row[r] = l_row[r] * alpha + rs;
                m_row[r] = m_new;
                alpha_s[r] = alpha;
            }
            PsT[lane * 68 + r]        = p0;
            PsT[(lane + 32) * 68 + r] = p1;
        }
        __syncthreads();

        // ---- O = O*alpha + P @ V  (4x4 per thread)
        {
#pragma unroll
            for (int i = 0; i < 4; i++) {
                float al = alpha_s[ty * 4 + i];
#pragma unroll
                for (int j = 0; j < 4; j++) accO[i][j] *= al;
            }
#pragma unroll 8
            for (int j = 0; j < 64; j++) {
                float pf[4], vf[4];
                *(float4*)(pf) = *(const float4*)(PsT + j * 68 + ty * 4);
                *(float4*)(vf) = *(const float4*)(Vs + j * 68 + tx * 4);
#pragma unroll
                for (int i = 0; i < 4; i++)
#pragma unroll
                    for (int c = 0; c < 4; c++)
                        accO[i][c] += pf[i] * vf[c];
            }
        }
        __syncthreads();
    }

    // ---- normalize and write to g_att in token order (undoes region permute)
#pragma unroll
    for (int i = 0; i < 4; i++) {
        int r = ty * 4 + i;
        float inv = 1.0f / l_row[r];
        int l = tok_index(rg, i0 + r);
        *(float4*)(g_att + (size_t)l * DIMC + h * HD + tx * 4) =
            make_float4(accO[i][0] * inv, accO[i][1] * inv,
                        accO[i][2] * inv, accO[i][3] * inv);
    }
}

// ---------------------------------------------------------------------------
extern "C" void kernel_launch(void* const* d_in, const int* in_sizes, int n_in,
                              void* d_out, int out_size) {
    const float* x      = (const float*)d_in[0];
    const float* qkv_w  = (const float*)d_in[1];
    const float* qkv_b  = (const float*)d_in[2];
    const float* proj_w = (const float*)d_in[3];
    const float* proj_b = (const float*)d_in[4];
    const float* epeg_w = (const float*)d_in[5];
    const float* epeg_b = (const float*)d_in[6];
    float* out = (float*)d_out;

    float* qkv_buf = nullptr;
    float* att_buf = nullptr;
    cudaGetSymbolAddress((void**)&qkv_buf, g_qkv);
    cudaGetSymbolAddress((void**)&att_buf, g_att);

    cudaFuncSetAttribute(region_attn_kernel,
                         cudaFuncAttributeMaxDynamicSharedMemorySize,
                         SMEM_ATTN_BYTES);

    dim3 blk(256);

    // qkv = x @ qkv_w^T + qkv_b
    gemm_bias_kernel<<<dim3(QKVC / 128, LTOK / 128), blk>>>(
        x, qkv_w, qkv_b, qkv_buf, LTOK, QKVC, DIMC);

    // fused region attention (writes g_att in token order)
    region_attn_kernel<<<dim3(16, NH, 16), blk, SMEM_ATTN_BYTES>>>(epeg_w, epeg_b);

    // out = att @ proj_w^T + proj_b
    gemm_bias_kernel<<<dim3(DIMC / 128, LTOK / 128), blk>>>(
        att_buf, proj_w, proj_b, out, LTOK, DIMC, DIMC);
}

// round 4
// speedup vs baseline: 1.1379x; 1.0177x over previous
#include <cuda_runtime.h>

// ---------------------------------------------------------------------------
// RegionAttention: x(16384,512) -> qkv gemm -> per-(region,head) attention with
// EPEG conv (depthwise k=5 along query axis) + softmax -> proj gemm -> out.
// 16 regions x 1024 tokens, 8 heads x 64 dim. All fp32.
// R4: attention pipeline restructured: 2 barriers/j-tile (was 4),
//     K/V prefetched into registers during S-compute, V double-buffered.
// ---------------------------------------------------------------------------

#define LTOK   16384
#define DIMC   512
#define QKVC   1536
#define NH     8
#define HD     64
#define NREG   1024
#define SCALE_Q 0.125f   // 64^-0.5

__device__ float g_qkv[LTOK * QKVC];   // (l, 3*512): q at +0, k at +512, v at +1024
__device__ float g_att[LTOK * DIMC];   // attention output in token order

// region token (rg, n) -> original token index l
__device__ __forceinline__ int tok_index(int rg, int n) {
    return ((rg >> 2) << 12) | ((n >> 5) << 7) | ((rg & 3) << 5) | (n & 31);
}

// ---------------------------------------------------------------------------
// Generic C[m,n] = sum_k A[m,k] * W[n,k] + bias[n]
// BM=BN=128, BK=16, 256 threads, 8x8 per thread. (unchanged control)
// ---------------------------------------------------------------------------
__global__ __launch_bounds__(256) void gemm_bias_kernel(
    const float* __restrict__ A, const float* __restrict__ W,
    const float* __restrict__ bias, float* __restrict__ C,
    int M, int N, int K)
{
    __shared__ float AsT[16][132];
    __shared__ float WsT[16][132];

    const int tid = threadIdx.x;
    const int m0 = blockIdx.y << 7;
    const int n0 = blockIdx.x << 7;
    const int ty = tid >> 4;
    const int tx = tid & 15;
    const int lr = tid >> 2;
    const int lc = (tid & 3) << 2;

    float acc[8][8];
#pragma unroll
    for (int i = 0; i < 8; i++)
#pragma unroll
        for (int j = 0; j < 8; j++) acc[i][j] = 0.f;

    const float* Ap = A + (size_t)(m0 + lr) * K + lc;
    const float* Wp = W + (size_t)(n0 + lr) * K + lc;

    for (int k0 = 0; k0 < K; k0 += 16) {
        float4 a0 = *(const float4*)(Ap + k0);
        float4 a1 = *(const float4*)(Ap + (size_t)64 * K + k0);
        float4 w0 = *(const float4*)(Wp + k0);
        float4 w1 = *(const float4*)(Wp + (size_t)64 * K + k0);
        __syncthreads();
        AsT[lc + 0][lr] = a0.x; AsT[lc + 1][lr] = a0.y;
        AsT[lc + 2][lr] = a0.z; AsT[lc + 3][lr] = a0.w;
        AsT[lc + 0][lr + 64] = a1.x; AsT[lc + 1][lr + 64] = a1.y;
        AsT[lc + 2][lr + 64] = a1.z; AsT[lc + 3][lr + 64] = a1.w;
        WsT[lc + 0][lr] = w0.x; WsT[lc + 1][lr] = w0.y;
        WsT[lc + 2][lr] = w0.z; WsT[lc + 3][lr] = w0.w;
        WsT[lc + 0][lr + 64] = w1.x; WsT[lc + 1][lr + 64] = w1.y;
        WsT[lc + 2][lr + 64] = w1.z; WsT[lc + 3][lr + 64] = w1.w;
        __syncthreads();
#pragma unroll 8
        for (int kk = 0; kk < 16; kk++) {
            float af[8], wf[8];
            *(float4*)(af)     = *(const float4*)(&AsT[kk][ty * 8]);
            *(float4*)(af + 4) = *(const float4*)(&AsT[kk][ty * 8 + 4]);
            *(float4*)(wf)     = *(const float4*)(&WsT[kk][tx * 8]);
            *(float4*)(wf + 4) = *(const float4*)(&WsT[kk][tx * 8 + 4]);
#pragma unroll
            for (int i = 0; i < 8; i++)
#pragma unroll
                for (int j = 0; j < 8; j++)
                    acc[i][j] += af[i] * wf[j];
        }
    }

    float bv[8];
#pragma unroll
    for (int j = 0; j < 8; j++) bv[j] = bias[n0 + tx * 8 + j];

#pragma unroll
    for (int i = 0; i < 8; i++) {
        float* Cp = C + (size_t)(m0 + ty * 8 + i) * N + n0 + tx * 8;
        *(float4*)(Cp)     = make_float4(acc[i][0] + bv[0], acc[i][1] + bv[1],
                                         acc[i][2] + bv[2], acc[i][3] + bv[3]);
        *(float4*)(Cp + 4) = make_float4(acc[i][4] + bv[4], acc[i][5] + bv[5],
                                         acc[i][6] + bv[6], acc[i][7] + bv[7]);
    }
}

// ---------------------------------------------------------------------------
// Fused region attention, 64-row Q tiles, 2 barriers per j-tile.
// grid: (row_tile 0..15, head 0..7, region 0..15), 256 threads, 2 CTAs/SM.
// ---------------------------------------------------------------------------
// smem float offsets
#define OFF_QST   0        // [64 d][72]  cols 0..63 main rows, 64..67 halo
#define OFF_KST   4608     // [64 d][68]  (single buffer)
#define OFF_VS0   8960     // [64 j][68]  buffer 0
#define OFF_VS1   13312    // [64 j][68]  buffer 1
#define OFF_SS    17664    // [68 p][68]  p <-> region row i0-2+p
#define OFF_PST   22288    // [64 j][68]  (j, row)
#define OFF_ALPHA 26640    // [64]
#define OFF_M     26704    // [64]
#define OFF_L     26768    // [64]
#define SMEM_ATTN_FLOATS 26832
#define SMEM_ATTN_BYTES (SMEM_ATTN_FLOATS * 4)   // 107328 B

__global__ __launch_bounds__(256) void region_attn_kernel(
    const float* __restrict__ epeg_w, const float* __restrict__ epeg_b)
{
    extern __shared__ float sm[];
    float* QsT     = sm + OFF_QST;
    float* KsT     = sm + OFF_KST;
    float* Ss      = sm + OFF_SS;
    float* PsT     = sm + OFF_PST;
    float* alpha_s = sm + OFF_ALPHA;
    float* m_row   = sm + OFF_M;
    float* l_row   = sm + OFF_L;

    const int tid  = threadIdx.x;
    const int it   = blockIdx.x;
    const int h    = blockIdx.y;
    const int rg   = blockIdx.z;
    const int i0   = it << 6;

    const int ty   = tid >> 4;   // 0..15
    const int tx   = tid & 15;   // 0..15
    const int warp = tid >> 5;   // 0..7
    const int lane = tid & 31;

    const float cw0 = epeg_w[h * 5 + 0];
    const float cw1 = epeg_w[h * 5 + 1];
    const float cw2 = epeg_w[h * 5 + 2];
    const float cw3 = epeg_w[h * 5 + 3];
    const float cw4 = epeg_w[h * 5 + 4];
    const float cb  = epeg_b[h];

    if (tid < 64) { m_row[tid] = -3.0e38f; l_row[tid] = 0.f; }

    // this thread's 4 (j, c4) load slots: j = loader row, c4 = dim base
    const int ld_j0 = tid >> 4;          // rows tid>>4, +16, +32, +48
    const int ld_c4 = (tid & 15) << 2;   // 0..60

    // ---- load Q (scaled), transposed to (d, row-col); zero out-of-region halo
    for (int idx = tid; idx < 68 * 16; idx += 256) {
        int p  = idx >> 4;
        int c4 = (idx & 15) << 2;
        int col = (p < 2) ? (64 + p) : ((p < 66) ? (p - 2) : p);
        int ireg = i0 - 2 + p;
        float4 q = make_float4(0.f, 0.f, 0.f, 0.f);
        if (ireg >= 0 && ireg < NREG) {
            int l = tok_index(rg, ireg);
            q = *(const float4*)(g_qkv + (size_t)l * QKVC + h * HD + c4);
        }
        QsT[(c4 + 0) * 72 + col] = q.x * SCALE_Q;
        QsT[(c4 + 1) * 72 + col] = q.y * SCALE_Q;
        QsT[(c4 + 2) * 72 + col] = q.z * SCALE_Q;
        QsT[(c4 + 3) * 72 + col] = q.w * SCALE_Q;
    }

    // ---- preload tile 0 K/V directly into smem (K single buf, V buf 0)
    {
        float* Vs0 = sm + OFF_VS0;
#pragma unroll
        for (int s = 0; s < 4; s++) {
            int j = ld_j0 + s * 16;
            int l = tok_index(rg, j);
            const float* base = g_qkv + (size_t)l * QKVC + h * HD + ld_c4;
            float4 k4 = *(const float4*)(base + 512);
            float4 v4 = *(const float4*)(base + 1024);
            KsT[(ld_c4 + 0) * 68 + j] = k4.x;
            KsT[(ld_c4 + 1) * 68 + j] = k4.y;
            KsT[(ld_c4 + 2) * 68 + j] = k4.z;
            KsT[(ld_c4 + 3) * 68 + j] = k4.w;
            *(float4*)(Vs0 + j * 68 + ld_c4) = v4;
        }
    }

    float accO[4][4];
#pragma unroll
    for (int i = 0; i < 4; i++)
#pragma unroll
        for (int j = 0; j < 4; j++) accO[i][j] = 0.f;

    __syncthreads();

    for (int jt = 0; jt < 16; jt++) {
        float* Vcur = sm + (((jt & 1) == 0) ? OFF_VS0 : OFF_VS1);
        float* Vnxt = sm + (((jt & 1) == 0) ? OFF_VS1 : OFF_VS0);

        // ---- issue next tile's K/V gmem loads into registers (in flight
        //      during S compute). jt=15 prefetches tile 0 harmlessly.
        float4 kreg[4], vreg[4];
        {
            int jn = ((jt + 1) & 15) << 6;
#pragma unroll
            for (int s = 0; s < 4; s++) {
                int l = tok_index(rg, jn + ld_j0 + s * 16);
                const float* base = g_qkv + (size_t)l * QKVC + h * HD + ld_c4;
                kreg[s] = *(const float4*)(base + 512);
                vreg[s] = *(const float4*)(base + 1024);
            }
        }

        // ---- S = Qscaled @ K^T : main 64x64 (4x4 per thread) + 4 halo rows
        {
            float accS[4][4];
#pragma unroll
            for (int i = 0; i < 4; i++)
#pragma unroll
                for (int j = 0; j < 4; j++) accS[i][j] = 0.f;

#pragma unroll 8
            for (int d = 0; d < 64; d++) {
                float af[4], bf[4];
                *(float4*)(af) = *(const float4*)(QsT + d * 72 + ty * 4);
                *(float4*)(bf) = *(const float4*)(KsT + d * 68 + tx * 4);
#pragma unroll
                for (int i = 0; i < 4; i++)
#pragma unroll
                    for (int j = 0; j < 4; j++)
                        accS[i][j] += af[i] * bf[j];
            }
#pragma unroll
            for (int i = 0; i < 4; i++) {
                *(float4*)(Ss + (ty * 4 + i + 2) * 68 + tx * 4) =
                    make_float4(accS[i][0], accS[i][1], accS[i][2], accS[i][3]);
            }

            int hr = tid >> 6;      // 0..3
            int j  = tid & 63;
            float a = 0.f;
#pragma unroll 8
            for (int d = 0; d < 64; d++)
                a += QsT[d * 72 + 64 + hr] * KsT[d * 68 + j];
            int ps = (hr < 2) ? hr : (64 + hr);   // 0,1,66,67
            Ss[ps * 68 + j] = a;
        }
        __syncthreads();   // sync1: S visible to conv readers; K readers done

        // ---- store prefetched next-tile K (single buf, safe now) and V (alt buf)
#pragma unroll
        for (int s = 0; s < 4; s++) {
            int j = ld_j0 + s * 16;
            KsT[(ld_c4 + 0) * 68 + j] = kreg[s].x;
            KsT[(ld_c4 + 1) * 68 + j] = kreg[s].y;
            KsT[(ld_c4 + 2) * 68 + j] = kreg[s].z;
            KsT[(ld_c4 + 3) * 68 + j] = kreg[s].w;
            *(float4*)(Vnxt + j * 68 + ld_c4) = vreg[s];
        }

        // ---- conv + bias + online softmax (warp w owns rows w*8..w*8+7)
        for (int rr = 0; rr < 8; rr++) {
            int r = (warp << 3) + rr;
            float lg0, lg1;
            {
                int j = lane;
                float s0 = Ss[(r + 0) * 68 + j];
                float s1 = Ss[(r + 1) * 68 + j];
                float s2 = Ss[(r + 2) * 68 + j];
                float s3 = Ss[(r + 3) * 68 + j];
                float s4 = Ss[(r + 4) * 68 + j];
                lg0 = s2 + cb + cw0 * s0 + cw1 * s1 + cw2 * s2 + cw3 * s3 + cw4 * s4;
            }
            {
                int j = lane + 32;
                float s0 = Ss[(r + 0) * 68 + j];
                float s1 = Ss[(r + 1) * 68 + j];
                float s2 = Ss[(r + 2) * 68 + j];
                float s3 = Ss[(r + 3) * 68 + j];
                float s4 = Ss[(r + 4) * 68 + j];
                lg1 = s2 + cb + cw0 * s0 + cw1 * s1 + cw2 * s2 + cw3 * s3 + cw4 * s4;
            }
            float mx = fmaxf(lg0, lg1);
#pragma unroll
            for (int off = 16; off > 0; off >>= 1)
                mx = fmaxf(mx, __shfl_xor_sync(0xffffffffu, mx, off));
            float m_old = m_row[r];
            float m_new = fmaxf(m_old, mx);
            float p0 = __expf(lg0 - m_new);
            float p1 = __expf(lg1 - m_new);
            float rs = p0 + p1;
#pragma unroll
            for (int off = 16; off > 0; off >>= 1)
                rs += __shfl_xor_sync(0xffffffffu, rs, off);
            if (lane == 0) {
                float alpha = __expf(m_old - m_new);
                l_row[r] = l_row[r] * alpha + rs;
                m_row[r] = m_new;
                alpha_s[r] = alpha;
            }
            PsT[lane * 68 + r]        = p0;
            PsT[(lane + 32) * 68 + r] = p1;
        }
        __syncthreads();   // sync2: P + next K/V visible

        // ---- O = O*alpha + P @ V  (4x4 per thread)
        {
#pragma unroll
            for (int i = 0; i < 4; i++) {
                float al = alpha_s[ty * 4 + i];
#pragma unroll
                for (int j = 0; j < 4; j++) accO[i][j] *= al;
            }
#pragma unroll 8
            for (int j = 0; j < 64; j++) {
                float pf[4], vf[4];
                *(float4*)(pf) = *(const float4*)(PsT + j * 68 + ty * 4);
                *(float4*)(vf) = *(const float4*)(Vcur + j * 68 + tx * 4);
#pragma unroll
                for (int i = 0; i < 4; i++)
#pragma unroll
                    for (int c = 0; c < 4; c++)
                        accO[i][c] += pf[i] * vf[c];
            }
        }
        // no barrier: next S-phase reads KsT (stored pre-sync2) & writes Ss
        // (conv readers finished pre-sync2); PsT next written after sync1.
    }

    // ---- normalize and write to g_att in token order (undoes region permute)
#pragma unroll
    for (int i = 0; i < 4; i++) {
        int r = ty * 4 + i;
        float inv = 1.0f / l_row[r];
        int l = tok_index(rg, i0 + r);
        *(float4*)(g_att + (size_t)l * DIMC + h * HD + tx * 4) =
            make_float4(accO[i][0] * inv, accO[i][1] * inv,
                        accO[i][2] * inv, accO[i][3] * inv);
    }
}

// ---------------------------------------------------------------------------
extern "C" void kernel_launch(void* const* d_in, const int* in_sizes, int n_in,
                              void* d_out, int out_size) {
    const float* x      = (const float*)d_in[0];
    const float* qkv_w  = (const float*)d_in[1];
    const float* qkv_b  = (const float*)d_in[2];
    const float* proj_w = (const float*)d_in[3];
    const float* proj_b = (const float*)d_in[4];
    const float* epeg_w = (const float*)d_in[5];
    const float* epeg_b = (const float*)d_in[6];
    float* out = (float*)d_out;

    float* qkv_buf = nullptr;
    float* att_buf = nullptr;
    cudaGetSymbolAddress((void**)&qkv_buf, g_qkv);
    cudaGetSymbolAddress((void**)&att_buf, g_att);

    cudaFuncSetAttribute(region_attn_kernel,
                         cudaFuncAttributeMaxDynamicSharedMemorySize,
                         SMEM_ATTN_BYTES);

    dim3 blk(256);

    // qkv = x @ qkv_w^T + qkv_b
    gemm_bias_kernel<<<dim3(QKVC / 128, LTOK / 128), blk>>>(
        x, qkv_w, qkv_b, qkv_buf, LTOK, QKVC, DIMC);

    // fused region attention (writes g_att in token order)
    region_attn_kernel<<<dim3(16, NH, 16), blk, SMEM_ATTN_BYTES>>>(epeg_w, epeg_b);

    // out = att @ proj_w^T + proj_b
    gemm_bias_kernel<<<dim3(DIMC / 128, LTOK / 128), blk>>>(
        att_buf, proj_w, proj_b, out, LTOK, DIMC, DIMC);
}

// round 6
// speedup vs baseline: 1.4117x; 1.2406x over previous
#include <cuda_runtime.h>
#include <cuda_bf16.h>
#include <cstdint>

// ---------------------------------------------------------------------------
// RegionAttention: x(16384,512) -> qkv gemm -> per-(region,head) attention with
// EPEG conv (depthwise k=5 along query axis) + softmax -> proj gemm -> out.
// R6: dense GEMMs on mma.sync.m16n8k16 bf16 (sm_80 PTX, compiles at sm_100)
//     with hi/lo split 3-term compensation, fp32 accumulate.
//     (tcgen05 rejected: harness builds plain sm_100, no 'a' features.)
//     Attention kernel unchanged (control).
// ---------------------------------------------------------------------------

#define LTOK   16384
#define DIMC   512
#define QKVC   1536
#define NH     8
#define HD     64
#define NREG   1024
#define SCALE_Q 0.125f   // 64^-0.5

__device__ float g_qkv[LTOK * QKVC];   // (l, 3*512): q at +0, k at +512, v at +1024
__device__ float g_att[LTOK * DIMC];   // attention output in token order

// region token (rg, n) -> original token index l
__device__ __forceinline__ int tok_index(int rg, int n) {
    return ((rg >> 2) << 12) | ((n >> 5) << 7) | ((rg & 3) << 5) | (n & 31);
}

// ===========================================================================
// mma.sync bf16 GEMM: C[m,n] = sum_k A[m,k]*W[n,k] + bias[n]
// fp32 in/out; bf16 hi/lo split, 3 terms (AhWh + AhWl + AlWh), fp32 acc.
// CTA tile 128x128, K-chunk 64, 256 threads = 8 warps (2m x 4n), warp 64x32.
// ===========================================================================

__device__ __forceinline__ void mma16816(float c[4],
                                         uint32_t a0, uint32_t a1,
                                         uint32_t a2, uint32_t a3,
                                         uint32_t b0, uint32_t b1) {
    asm volatile(
        "mma.sync.aligned.m16n8k16.row.col.f32.bf16.bf16.f32 "
        "{%0,%1,%2,%3}, {%4,%5,%6,%7}, {%8,%9}, {%0,%1,%2,%3};"
        : "+f"(c[0]), "+f"(c[1]), "+f"(c[2]), "+f"(c[3])
        : "r"(a0), "r"(a1), "r"(a2), "r"(a3), "r"(b0), "r"(b1));
}

// smem bf16-element offsets (stride 72 per row: conflict-free fragment LDS)
#define GSTRIDE 72
#define GOFF_AHI 0
#define GOFF_ALO (128 * GSTRIDE)
#define GOFF_WHI (2 * 128 * GSTRIDE)
#define GOFF_WLO (3 * 128 * GSTRIDE)
#define GEMM_SMEM_BYTES (4 * 128 * GSTRIDE * 2)   // 73728

__global__ __launch_bounds__(256) void gemm_mma_kernel(
    const float* __restrict__ A, const float* __restrict__ W,
    const float* __restrict__ bias, float* __restrict__ C,
    int M, int N, int K)
{
    extern __shared__ char smc[];
    __nv_bfloat16* sb = (__nv_bfloat16*)smc;

    const int tid  = threadIdx.x;
    const int m0   = blockIdx.y << 7;
    const int n0   = blockIdx.x << 7;
    const int wid  = tid >> 5;
    const int lane = tid & 31;
    const int wm   = wid & 1;        // 0..1 -> m offset 0/64
    const int wn   = wid >> 1;       // 0..3 -> n offset 0/32/64/96

    const int lr = tid >> 4;         // loader row 0..15
    const int lc = (tid & 15) << 2;  // loader col base 0..60

    const int qrow = lane >> 2;      // 0..7
    const int qk2  = (lane & 3) << 1;// 0,2,4,6

    float acc[4][4][4];
#pragma unroll
    for (int i = 0; i < 4; i++)
#pragma unroll
        for (int j = 0; j < 4; j++)
#pragma unroll
            for (int c = 0; c < 4; c++) acc[i][j][c] = 0.f;

    const int nchunks = K >> 6;
    for (int kc = 0; kc < nchunks; kc++) {
        const int k0 = kc << 6;
        const float* Ab = A + (size_t)m0 * K + k0;
        const float* Wb = W + (size_t)n0 * K + k0;

        if (kc > 0) __syncthreads();   // protect smem from previous mma readers

        // ---- load 128x64 fp32 A and W, split bf16 hi/lo into padded smem
#pragma unroll
        for (int it = 0; it < 8; it++) {
            int r = it * 16 + lr;
            float4 a4 = *(const float4*)(Ab + (size_t)r * K + lc);
            float4 w4 = *(const float4*)(Wb + (size_t)r * K + lc);

            int base = r * GSTRIDE + lc;

            __nv_bfloat162 ah01 = __floats2bfloat162_rn(a4.x, a4.y);
            __nv_bfloat162 ah23 = __floats2bfloat162_rn(a4.z, a4.w);
            __nv_bfloat162 al01 = __floats2bfloat162_rn(a4.x - __low2float(ah01),
                                                        a4.y - __high2float(ah01));
            __nv_bfloat162 al23 = __floats2bfloat162_rn(a4.z - __low2float(ah23),
                                                        a4.w - __high2float(ah23));
            uint2 hv, lv;
            hv.x = *(uint32_t*)&ah01; hv.y = *(uint32_t*)&ah23;
            lv.x = *(uint32_t*)&al01; lv.y = *(uint32_t*)&al23;
            *(uint2*)(sb + GOFF_AHI + base) = hv;
            *(uint2*)(sb + GOFF_ALO + base) = lv;

            __nv_bfloat162 wh01 = __floats2bfloat162_rn(w4.x, w4.y);
            __nv_bfloat162 wh23 = __floats2bfloat162_rn(w4.z, w4.w);
            __nv_bfloat162 wl01 = __floats2bfloat162_rn(w4.x - __low2float(wh01),
                                                        w4.y - __high2float(wh01));
            __nv_bfloat162 wl23 = __floats2bfloat162_rn(w4.z - __low2float(wh23),
                                                        w4.w - __high2float(wh23));
            hv.x = *(uint32_t*)&wh01; hv.y = *(uint32_t*)&wh23;
            lv.x = *(uint32_t*)&wl01; lv.y = *(uint32_t*)&wl23;
            *(uint2*)(sb + GOFF_WHI + base) = hv;
            *(uint2*)(sb + GOFF_WLO + base) = lv;
        }
        __syncthreads();

        // ---- 4 k-steps of 16; per step: AhWh, AhWl, AlWh (16 atoms each)
#pragma unroll
        for (int ks = 0; ks < 4; ks++) {
            const int kb = ks * 16 + qk2;
            uint32_t a[4][4], bh[4][2], bl[4][2];

            // Ah fragments
#pragma unroll
            for (int i = 0; i < 4; i++) {
                int r0 = wm * 64 + i * 16 + qrow;
                a[i][0] = *(const uint32_t*)(sb + GOFF_AHI + r0 * GSTRIDE + kb);
                a[i][1] = *(const uint32_t*)(sb + GOFF_AHI + (r0 + 8) * GSTRIDE + kb);
                a[i][2] = *(const uint32_t*)(sb + GOFF_AHI + r0 * GSTRIDE + kb + 8);
                a[i][3] = *(const uint32_t*)(sb + GOFF_AHI + (r0 + 8) * GSTRIDE + kb + 8);
            }
            // Wh fragments
#pragma unroll
            for (int j = 0; j < 4; j++) {
                int nr = wn * 32 + j * 8 + qrow;
                bh[j][0] = *(const uint32_t*)(sb + GOFF_WHI + nr * GSTRIDE + kb);
                bh[j][1] = *(const uint32_t*)(sb + GOFF_WHI + nr * GSTRIDE + kb + 8);
            }
#pragma unroll
            for (int i = 0; i < 4; i++)
#pragma unroll
                for (int j = 0; j < 4; j++)
                    mma16816(acc[i][j], a[i][0], a[i][1], a[i][2], a[i][3],
                             bh[j][0], bh[j][1]);

            // Wl fragments: Ah * Wl
#pragma unroll
            for (int j = 0; j < 4; j++) {
                int nr = wn * 32 + j * 8 + qrow;
                bl[j][0] = *(const uint32_t*)(sb + GOFF_WLO + nr * GSTRIDE + kb);
                bl[j][1] = *(const uint32_t*)(sb + GOFF_WLO + nr * GSTRIDE + kb + 8);
            }
#pragma unroll
            for (int i = 0; i < 4; i++)
#pragma unroll
                for (int j = 0; j < 4; j++)
                    mma16816(acc[i][j], a[i][0], a[i][1], a[i][2], a[i][3],
                             bl[j][0], bl[j][1]);

            // Al fragments (overwrite a): Al * Wh
#pragma unroll
            for (int i = 0; i < 4; i++) {
                int r0 = wm * 64 + i * 16 + qrow;
                a[i][0] = *(const uint32_t*)(sb + GOFF_ALO + r0 * GSTRIDE + kb);
                a[i][1] = *(const uint32_t*)(sb + GOFF_ALO + (r0 + 8) * GSTRIDE + kb);
                a[i][2] = *(const uint32_t*)(sb + GOFF_ALO + r0 * GSTRIDE + kb + 8);
                a[i][3] = *(const uint32_t*)(sb + GOFF_ALO + (r0 + 8) * GSTRIDE + kb + 8);
            }
#pragma unroll
            for (int i = 0; i < 4; i++)
#pragma unroll
                for (int j = 0; j < 4; j++)
                    mma16816(acc[i][j], a[i][0], a[i][1], a[i][2], a[i][3],
                             bh[j][0], bh[j][1]);
        }
    }

    // ---- epilogue: acc + bias -> C
#pragma unroll
    for (int i = 0; i < 4; i++) {
        int gr = m0 + wm * 64 + i * 16 + qrow;
#pragma unroll
        for (int j = 0; j < 4; j++) {
            int gc = n0 + wn * 32 + j * 8 + qk2;
            float2 bv = *(const float2*)(bias + gc);
            float2 o0, o1;
            o0.x = acc[i][j][0] + bv.x; o0.y = acc[i][j][1] + bv.y;
            o1.x = acc[i][j][2] + bv.x; o1.y = acc[i][j][3] + bv.y;
            *(float2*)(C + (size_t)gr * N + gc)       = o0;
            *(float2*)(C + (size_t)(gr + 8) * N + gc) = o1;
        }
    }
}

// ---------------------------------------------------------------------------
// Fused region attention (unchanged from R4): 64-row Q tiles, 2 barriers/tile,
// register prefetch of next K/V, V double-buffered. 2 CTAs/SM.
// ---------------------------------------------------------------------------
#define OFF_QST   0
#define OFF_KST   4608
#define OFF_VS0   8960
#define OFF_VS1   13312
#define OFF_SS    17664
#define OFF_PST   22288
#define OFF_ALPHA 26640
#define OFF_M     26704
#define OFF_L     26768
#define SMEM_ATTN_FLOATS 26832
#define SMEM_ATTN_BYTES (SMEM_ATTN_FLOATS * 4)

__global__ __launch_bounds__(256) void region_attn_kernel(
    const float* __restrict__ epeg_w, const float* __restrict__ epeg_b)
{
    extern __shared__ char smc[];
    float* sm = (float*)smc;
    float* QsT     = sm + OFF_QST;
    float* KsT     = sm + OFF_KST;
    float* Ss      = sm + OFF_SS;
    float* PsT     = sm + OFF_PST;
    float* alpha_s = sm + OFF_ALPHA;
    float* m_row   = sm + OFF_M;
    float* l_row   = sm + OFF_L;

    const int tid  = threadIdx.x;
    const int it   = blockIdx.x;
    const int h    = blockIdx.y;
    const int rg   = blockIdx.z;
    const int i0   = it << 6;

    const int ty   = tid >> 4;
    const int tx   = tid & 15;
    const int warp = tid >> 5;
    const int lane = tid & 31;

    const float cw0 = epeg_w[h * 5 + 0];
    const float cw1 = epeg_w[h * 5 + 1];
    const float cw2 = epeg_w[h * 5 + 2];
    const float cw3 = epeg_w[h * 5 + 3];
    const float cw4 = epeg_w[h * 5 + 4];
    const float cb  = epeg_b[h];

    if (tid < 64) { m_row[tid] = -3.0e38f; l_row[tid] = 0.f; }

    const int ld_j0 = tid >> 4;
    const int ld_c4 = (tid & 15) << 2;

    for (int idx = tid; idx < 68 * 16; idx += 256) {
        int p  = idx >> 4;
        int c4 = (idx & 15) << 2;
        int col = (p < 2) ? (64 + p) : ((p < 66) ? (p - 2) : p);
        int ireg = i0 - 2 + p;
        float4 q = make_float4(0.f, 0.f, 0.f, 0.f);
        if (ireg >= 0 && ireg < NREG) {
            int l = tok_index(rg, ireg);
            q = *(const float4*)(g_qkv + (size_t)l * QKVC + h * HD + c4);
        }
        QsT[(c4 + 0) * 72 + col] = q.x * SCALE_Q;
        QsT[(c4 + 1) * 72 + col] = q.y * SCALE_Q;
        QsT[(c4 + 2) * 72 + col] = q.z * SCALE_Q;
        QsT[(c4 + 3) * 72 + col] = q.w * SCALE_Q;
    }

    {
        float* Vs0 = sm + OFF_VS0;
#pragma unroll
        for (int s = 0; s < 4; s++) {
            int j = ld_j0 + s * 16;
            int l = tok_index(rg, j);
            const float* base = g_qkv + (size_t)l * QKVC + h * HD + ld_c4;
            float4 k4 = *(const float4*)(base + 512);
            float4 v4 = *(const float4*)(base + 1024);
            KsT[(ld_c4 + 0) * 68 + j] = k4.x;
            KsT[(ld_c4 + 1) * 68 + j] = k4.y;
            KsT[(ld_c4 + 2) * 68 + j] = k4.z;
            KsT[(ld_c4 + 3) * 68 + j] = k4.w;
            *(float4*)(Vs0 + j * 68 + ld_c4) = v4;
        }
    }

    float accO[4][4];
#pragma unroll
    for (int i = 0; i < 4; i++)
#pragma unroll
        for (int j = 0; j < 4; j++) accO[i][j] = 0.f;

    __syncthreads();

    for (int jt = 0; jt < 16; jt++) {
        float* Vcur = sm + (((jt & 1) == 0) ? OFF_VS0 : OFF_VS1);
        float* Vnxt = sm + (((jt & 1) == 0) ? OFF_VS1 : OFF_VS0);

        float4 kreg[4], vreg[4];
        {
            int jn = ((jt + 1) & 15) << 6;
#pragma unroll
            for (int s = 0; s < 4; s++) {
                int l = tok_index(rg, jn + ld_j0 + s * 16);
                const float* base = g_qkv + (size_t)l * QKVC + h * HD + ld_c4;
                kreg[s] = *(const float4*)(base + 512);
                vreg[s] = *(const float4*)(base + 1024);
            }
        }

        {
            float accS[4][4];
#pragma unroll
            for (int i = 0; i < 4; i++)
#pragma unroll
                for (int j = 0; j < 4; j++) accS[i][j] = 0.f;

#pragma unroll 8
            for (int d = 0; d < 64; d++) {
                float af[4], bf[4];
                *(float4*)(af) = *(const float4*)(QsT + d * 72 + ty * 4);
                *(float4*)(bf) = *(const float4*)(KsT + d * 68 + tx * 4);
#pragma unroll
                for (int i = 0; i < 4; i++)
#pragma unroll
                    for (int j = 0; j < 4; j++)
                        accS[i][j] += af[i] * bf[j];
            }
#pragma unroll
            for (int i = 0; i < 4; i++) {
                *(float4*)(Ss + (ty * 4 + i + 2) * 68 + tx * 4) =
                    make_float4(accS[i][0], accS[i][1], accS[i][2], accS[i][3]);
            }

            int hr = tid >> 6;
            int j  = tid & 63;
            float a = 0.f;
#pragma unroll 8
            for (int d = 0; d < 64; d++)
                a += QsT[d * 72 + 64 + hr] * KsT[d * 68 + j];
            int ps = (hr < 2) ? hr : (64 + hr);
            Ss[ps * 68 + j] = a;
        }
        __syncthreads();

#pragma unroll
        for (int s = 0; s < 4; s++) {
            int j = ld_j0 + s * 16;
            KsT[(ld_c4 + 0) * 68 + j] = kreg[s].x;
            KsT[(ld_c4 + 1) * 68 + j] = kreg[s].y;
            KsT[(ld_c4 + 2) * 68 + j] = kreg[s].z;
            KsT[(ld_c4 + 3) * 68 + j] = kreg[s].w;
            *(float4*)(Vnxt + j * 68 + ld_c4) = vreg[s];
        }

        for (int rr = 0; rr < 8; rr++) {
            int r = (warp << 3) + rr;
            float lg0, lg1;
            {
                int j = lane;
                float s0 = Ss[(r + 0) * 68 + j];
                float s1 = Ss[(r + 1) * 68 + j];
                float s2 = Ss[(r + 2) * 68 + j];
                float s3 = Ss[(r + 3) * 68 + j];
                float s4 = Ss[(r + 4) * 68 + j];
                lg0 = s2 + cb + cw0 * s0 + cw1 * s1 + cw2 * s2 + cw3 * s3 + cw4 * s4;
            }
            {
                int j = lane + 32;
                float s0 = Ss[(r + 0) * 68 + j];
                float s1 = Ss[(r + 1) * 68 + j];
                float s2 = Ss[(r + 2) * 68 + j];
                float s3 = Ss[(r + 3) * 68 + j];
                float s4 = Ss[(r + 4) * 68 + j];
                lg1 = s2 + cb + cw0 * s0 + cw1 * s1 + cw2 * s2 + cw3 * s3 + cw4 * s4;
            }
            float mx = fmaxf(lg0, lg1);
#pragma unroll
            for (int off = 16; off > 0; off >>= 1)
                mx = fmaxf(mx, __shfl_xor_sync(0xffffffffu, mx, off));
            float m_old = m_row[r];
            float m_new = fmaxf(m_old, mx);
            float p0 = __expf(lg0 - m_new);
            float p1 = __expf(lg1 - m_new);
            float rs = p0 + p1;
#pragma unroll
            for (int off = 16; off > 0; off >>= 1)
                rs += __shfl_xor_sync(0xffffffffu, rs, off);
            if (lane == 0) {
                float alpha = __expf(m_old - m_new);
                l_row[r] = l_row[r] * alpha + rs;
                m_row[r] = m_new;
                alpha_s[r] = alpha;
            }
            PsT[lane * 68 + r]        = p0;
            PsT[(lane + 32) * 68 + r] = p1;
        }
        __syncthreads();

        {
#pragma unroll
            for (int i = 0; i < 4; i++) {
                float al = alpha_s[ty * 4 + i];
#pragma unroll
                for (int j = 0; j < 4; j++) accO[i][j] *= al;
            }
#pragma unroll 8
            for (int j = 0; j < 64; j++) {
                float pf[4], vf[4];
                *(float4*)(pf) = *(const float4*)(PsT + j * 68 + ty * 4);
                *(float4*)(vf) = *(const float4*)(Vcur + j * 68 + tx * 4);
#pragma unroll
                for (int i = 0; i < 4; i++)
#pragma unroll
                    for (int c = 0; c < 4; c++)
                        accO[i][c] += pf[i] * vf[c];
            }
        }
    }

#pragma unroll
    for (int i = 0; i < 4; i++) {
        int r = ty * 4 + i;
        float inv = 1.0f / l_row[r];
        int l = tok_index(rg, i0 + r);
        *(float4*)(g_att + (size_t)l * DIMC + h * HD + tx * 4) =
            make_float4(accO[i][0] * inv, accO[i][1] * inv,
                        accO[i][2] * inv, accO[i][3] * inv);
    }
}

// ---------------------------------------------------------------------------
extern "C" void kernel_launch(void* const* d_in, const int* in_sizes, int n_in,
                              void* d_out, int out_size) {
    const float* x      = (const float*)d_in[0];
    const float* qkv_w  = (const float*)d_in[1];
    const float* qkv_b  = (const float*)d_in[2];
    const float* proj_w = (const float*)d_in[3];
    const float* proj_b = (const float*)d_in[4];
    const float* epeg_w = (const float*)d_in[5];
    const float* epeg_b = (const float*)d_in[6];
    float* out = (float*)d_out;

    float* qkv_buf = nullptr;
    float* att_buf = nullptr;
    cudaGetSymbolAddress((void**)&qkv_buf, g_qkv);
    cudaGetSymbolAddress((void**)&att_buf, g_att);

    cudaFuncSetAttribute(gemm_mma_kernel,
                         cudaFuncAttributeMaxDynamicSharedMemorySize,
                         GEMM_SMEM_BYTES);
    cudaFuncSetAttribute(region_attn_kernel,
                         cudaFuncAttributeMaxDynamicSharedMemorySize,
                         SMEM_ATTN_BYTES);

    // qkv = x @ qkv_w^T + qkv_b   (bf16 mma.sync, hi/lo split)
    gemm_mma_kernel<<<dim3(QKVC / 128, LTOK / 128), 256, GEMM_SMEM_BYTES>>>(
        x, qkv_w, qkv_b, qkv_buf, LTOK, QKVC, DIMC);

    // fused region attention (writes g_att in token order)
    region_attn_kernel<<<dim3(16, NH, 16), 256, SMEM_ATTN_BYTES>>>(epeg_w, epeg_b);

    // out = att @ proj_w^T + proj_b   (bf16 mma.sync, hi/lo split)
    gemm_mma_kernel<<<dim3(DIMC / 128, LTOK / 128), 256, GEMM_SMEM_BYTES>>>(
        att_buf, proj_w, proj_b, out, LTOK, DIMC, DIMC);
}